// round 7
// baseline (speedup 1.0000x reference)
#include <cuda_runtime.h>

// Problem constants (from reference setup_inputs)
#define B 8
#define H 100
#define W 100
#define C 512
#define R 300
#define POOL 7

// grid: (R, POOL, B). One block per (roi, py) row.
// 128 threads split into two 64-thread halves; each half processes the px
// cells of its parity (cid=0: 0,2,4,6; cid=1: 1,3,5). Each thread handles
// 8 channels as two float4s at c and c+256 (shared base register, fully
// coalesced) -> 8 independent LDG.128 in flight per iteration.
__global__ __launch_bounds__(128, 9) void roi_align_kernel(
    const float* __restrict__ x,     // (B, H, W, C)
    const int*   __restrict__ rois,  // (R, 4): x1, y1, w, h
    float*       __restrict__ out)   // (B, R, 7, 7, C)
{
    const int r  = blockIdx.x;
    const int py = blockIdx.y;
    const int b  = blockIdx.z;

    const int4 roi = __ldg(((const int4*)rois) + r);
    const int x1 = roi.x, y1 = roi.y, w = roi.z, h = roi.w;

    // --- y axis coords, once per block (replicates JAX fp32 math) ---
    const float sh = (float)h;
    float vy = fmaf((float)py + 0.5f, sh * (1.0f / POOL), -0.5f);
    vy = fminf(fmaxf(vy, 0.0f), sh - 1.0f);
    const float fly = floorf(vy);
    const int   ylo = (int)fly;
    const float fy  = vy - fly;
    const int   yhi = min(ylo + 1, h - 1);

    // x-axis common subexpressions
    const float sw   = (float)w;
    const float stpx = sw * (1.0f / POOL);
    const float clx  = sw - 1.0f;
    const int   xmax = w - 1;

    const int cid = threadIdx.x >> 6;          // px parity (0 or 1)
    const int c   = (threadIdx.x & 63) * 4;    // channel base (first half)

    // 32-bit element offsets (max < 2^31)
    const unsigned rowl_off = (unsigned)(b * (H * W) + (y1 + ylo) * W) * C + c;
    const unsigned rowh_off = (unsigned)(b * (H * W) + (y1 + yhi) * W) * C + c;
    const unsigned out_base = (unsigned)((b * R + r) * 49 + py * POOL) * C + c;

    const float gy = 1.0f - fy;

    #pragma unroll
    for (int i = 0; i < 4; ++i) {
        const int px = 2 * i + cid;
        if (px < POOL) {
            // --- x axis coords for this cell ---
            float vx = fmaf((float)px + 0.5f, stpx, -0.5f);
            vx = fminf(fmaxf(vx, 0.0f), clx);
            float flx = floorf(vx);
            int   xlo = (int)flx;
            float fx  = vx - flx;
            int   xhi = min(xlo + 1, xmax);

            const unsigned ol = (unsigned)(x1 + xlo) * C;
            const unsigned oh = (unsigned)(x1 + xhi) * C;

            const float* ptl = x + rowl_off + ol;
            const float* ptr_ = x + rowl_off + oh;
            const float* pbl = x + rowh_off + ol;
            const float* pbr = x + rowh_off + oh;

            // 8 independent LDG.128 (pairs share a base register: [R],[R+1KB])
            float4 tl0 = *(const float4*)(ptl);
            float4 tl1 = *(const float4*)(ptl + 256);
            float4 tr0 = *(const float4*)(ptr_);
            float4 tr1 = *(const float4*)(ptr_ + 256);
            float4 bl0 = *(const float4*)(pbl);
            float4 bl1 = *(const float4*)(pbl + 256);
            float4 br0 = *(const float4*)(pbr);
            float4 br1 = *(const float4*)(pbr + 256);

            // bilinear weights
            const float gx = 1.0f - fx;
            const float w_tl = gx * gy;
            const float w_tr = fx * gy;
            const float w_bl = gx * fy;
            const float w_br = fx * fy;

            float4 o0, o1;
            o0.x = fmaf(br0.x, w_br, fmaf(bl0.x, w_bl, fmaf(tr0.x, w_tr, tl0.x * w_tl)));
            o0.y = fmaf(br0.y, w_br, fmaf(bl0.y, w_bl, fmaf(tr0.y, w_tr, tl0.y * w_tl)));
            o0.z = fmaf(br0.z, w_br, fmaf(bl0.z, w_bl, fmaf(tr0.z, w_tr, tl0.z * w_tl)));
            o0.w = fmaf(br0.w, w_br, fmaf(bl0.w, w_bl, fmaf(tr0.w, w_tr, tl0.w * w_tl)));
            o1.x = fmaf(br1.x, w_br, fmaf(bl1.x, w_bl, fmaf(tr1.x, w_tr, tl1.x * w_tl)));
            o1.y = fmaf(br1.y, w_br, fmaf(bl1.y, w_bl, fmaf(tr1.y, w_tr, tl1.y * w_tl)));
            o1.z = fmaf(br1.z, w_br, fmaf(bl1.z, w_bl, fmaf(tr1.z, w_tr, tl1.z * w_tl)));
            o1.w = fmaf(br1.w, w_br, fmaf(bl1.w, w_bl, fmaf(tr1.w, w_tr, tl1.w * w_tl)));

            // output is never re-read: streaming stores
            float* po = out + out_base + (unsigned)px * C;
            __stcs((float4*)(po), o0);
            __stcs((float4*)(po + 256), o1);
        }
    }
}

extern "C" void kernel_launch(void* const* d_in, const int* in_sizes, int n_in,
                              void* d_out, int out_size)
{
    const float* x    = (const float*)d_in[0];
    const int*   rois = (const int*)d_in[1];
    float*       out  = (float*)d_out;

    dim3 grid(R, POOL, B);   // 16,800 blocks; z-slowest => per-batch L2 locality
    roi_align_kernel<<<grid, 128>>>(x, rois, out);
}